// round 4
// baseline (speedup 1.0000x reference)
#include <cuda_runtime.h>
#include <math.h>
#include <stdint.h>

#define N_ROWS 32768
#define M_COLS 2048
#define DIM    128
#define HEADS  8

// ---------------- scratch (__device__ globals; no allocations allowed) ----------------
__device__ float    g_W[DIM * DIM];          // sum over heads of Wq
__device__ float    g_bsum[DIM];             // 2 * sum over heads of bq
__device__ float    g_G[M_COLS * DIM];       // (c @ W) / sqrt(DIM)
__device__ float    g_beta[M_COLS];          // (c . b) / sqrt(DIM)
__device__ float    g_L[(size_t)N_ROWS * M_COLS];     // logits, 256 MB
__device__ uint32_t g_B[(size_t)N_ROWS * M_COLS];     // threefry bits, 256 MB
__device__ int      g_idx[N_ROWS];
__device__ float    g_acc[M_COLS * DIM];

// ---------------- K0a: fold heads of Wq / bq ----------------
__global__ void __launch_bounds__(128) prep_Wb_kernel(const float* __restrict__ Wq,
                                                      const float* __restrict__ bq) {
    int i = blockIdx.x;
    int j = threadIdx.x;
    float s = 0.f;
#pragma unroll
    for (int h = 0; h < HEADS; h++) s += Wq[(h * DIM + i) * DIM + j];
    g_W[i * DIM + j] = s;
    if (i == 0) {
        float t = 0.f;
#pragma unroll
        for (int h = 0; h < HEADS; h++) t += bq[h * DIM + j];
        g_bsum[j] = 2.0f * t;
    }
}

// ---------------- K0b: G = (c @ W)/sqrt(D), beta = (c . b)/sqrt(D) ----------------
__global__ void __launch_bounds__(128) prep_G_kernel(const float* __restrict__ c) {
    int m = blockIdx.x;
    int kq = threadIdx.x;
    __shared__ float cs[DIM];
    __shared__ float red[DIM];
    cs[kq] = c[m * DIM + kq];
    __syncthreads();
    const float inv = 0.08838834764831845f;  // 1/sqrt(128)
    float s = 0.f;
#pragma unroll 8
    for (int j = 0; j < DIM; j++) s = fmaf(cs[j], g_W[j * DIM + kq], s);
    g_G[m * DIM + kq] = s * inv;
    red[kq] = cs[kq] * g_bsum[kq];
    __syncthreads();
    for (int st = 64; st > 0; st >>= 1) {
        if (kq < st) red[kq] += red[kq + st];
        __syncthreads();
    }
    if (kq == 0) g_beta[m] = red[0] * inv;
}

// ---------------- threefry2x32 (JAX, key=(0,42)), partitionable path ----------------
__device__ __forceinline__ void threefry2x32_042(uint32_t x0, uint32_t x1,
                                                 uint32_t& o0, uint32_t& o1) {
    const uint32_t KS0 = 0u, KS1 = 42u, KS2 = 0x1BD11BDAu ^ 42u;
    x0 += KS0; x1 += KS1;
#define TF_R(r) { x0 += x1; x1 = __funnelshift_l(x1, x1, r); x1 ^= x0; }
    TF_R(13) TF_R(15) TF_R(26) TF_R(6)   x0 += KS1; x1 += KS2 + 1u;
    TF_R(17) TF_R(29) TF_R(16) TF_R(24)  x0 += KS2; x1 += KS0 + 2u;
    TF_R(13) TF_R(15) TF_R(26) TF_R(6)   x0 += KS0; x1 += KS1 + 3u;
    TF_R(17) TF_R(29) TF_R(16) TF_R(24)  x0 += KS1; x1 += KS2 + 4u;
    TF_R(13) TF_R(15) TF_R(26) TF_R(6)   x0 += KS2; x1 += KS0 + 5u;
#undef TF_R
    o0 = x0; o1 = x1;
}

__device__ __forceinline__ uint32_t tf_bits(uint32_t f) {
    uint32_t o0, o1;
    threefry2x32_042(0u, f, o0, o1);
    return o0 ^ o1;
}

__device__ __forceinline__ float gumbel_from_bits(uint32_t bits) {
    float u = __uint_as_float((bits >> 9) | 0x3f800000u) - 1.0f;
    u = fmaxf(u, 1.17549435e-38f);  // jax uniform minval = tiny
    return -logf(-logf(u));
}

// ---------------- K2: logits GEMM fused with threefry-bits generation --------------
// logits = (x1+k) @ G.T + beta. Threefry bits for the same (n,m) tile are generated
// in the GEMM's spare issue slots (FFMA pipe binds; IADD3/SHF/LOP3 ride the alu pipe).
#define BM 128
#define BN 128
#define BKK 32
__global__ void __launch_bounds__(256) logits_kernel(const float* __restrict__ x1,
                                                     const float* __restrict__ kk) {
    __shared__ float As[BKK][BM + 5];
    __shared__ float Bs[BKK][BN + 5];
    const int bm = blockIdx.y;
    const int bn = blockIdx.x;
    const int tid = threadIdx.x;
    const int tx = tid & 15;
    const int ty = tid >> 4;
    const int row0 = bm * BM;
    const int col0 = bn * BN;

    float acc[8][8];
#pragma unroll
    for (int i = 0; i < 8; i++)
#pragma unroll
        for (int j = 0; j < 8; j++) acc[i][j] = 0.f;

    const int lr = tid >> 3;          // 0..31
    const int lk = (tid & 7) * 4;     // 0,4,..,28

    // threefry tile assignment: per k0-iteration, 32 rows x 128 cols of bits.
    const int tf_r_off = tid >> 3;            // 0..31 (row within 32-row slab)
    const int tf_m0 = col0 + (tid & 7) * 16;  // 16 consecutive cols per thread

    for (int k0 = 0, iter = 0; k0 < DIM; k0 += BKK, iter++) {
#pragma unroll
        for (int i = 0; i < 4; i++) {
            int r = lr + i * 32;
            float4 a4 = *(const float4*)(x1 + (size_t)(row0 + r) * DIM + k0 + lk);
            float4 b4 = *(const float4*)(kk + (size_t)(row0 + r) * DIM + k0 + lk);
            As[lk + 0][r] = a4.x + b4.x;
            As[lk + 1][r] = a4.y + b4.y;
            As[lk + 2][r] = a4.z + b4.z;
            As[lk + 3][r] = a4.w + b4.w;
            float4 g4 = *(const float4*)(g_G + (size_t)(col0 + r) * DIM + k0 + lk);
            Bs[lk + 0][r] = g4.x;
            Bs[lk + 1][r] = g4.y;
            Bs[lk + 2][r] = g4.z;
            Bs[lk + 3][r] = g4.w;
        }
        __syncthreads();
#pragma unroll
        for (int k = 0; k < BKK; k++) {
            float a[8], b[8];
#pragma unroll
            for (int i = 0; i < 8; i++) a[i] = As[k][ty * 8 + i];
#pragma unroll
            for (int j = 0; j < 8; j++) b[j] = Bs[k][tx * 8 + j];
#pragma unroll
            for (int i = 0; i < 8; i++)
#pragma unroll
                for (int j = 0; j < 8; j++) acc[i][j] = fmaf(a[i], b[j], acc[i][j]);
        }
        // --- threefry bits for 32 rows of this tile (independent of the FMA chain;
        //     issues on the alu/fma-int pipes in the scheduler's spare slots) ---
        {
            int r = row0 + iter * 32 + tf_r_off;
            uint32_t fb = (uint32_t)r * (uint32_t)M_COLS + (uint32_t)tf_m0;
            uint32_t* outp = g_B + (size_t)r * M_COLS + tf_m0;
#pragma unroll
            for (int q = 0; q < 4; q++) {
                uint4 o;
                o.x = tf_bits(fb + q * 4 + 0);
                o.y = tf_bits(fb + q * 4 + 1);
                o.z = tf_bits(fb + q * 4 + 2);
                o.w = tf_bits(fb + q * 4 + 3);
                *(uint4*)(outp + q * 4) = o;
            }
        }
        __syncthreads();
    }

    float4 bet0 = *(const float4*)(g_beta + col0 + tx * 8);
    float4 bet1 = *(const float4*)(g_beta + col0 + tx * 8 + 4);
#pragma unroll
    for (int i = 0; i < 8; i++) {
        int r = row0 + ty * 8 + i;
        float* outp = g_L + (size_t)r * M_COLS + col0 + tx * 8;
        float4 w0 = make_float4(acc[i][0] + bet0.x, acc[i][1] + bet0.y,
                                acc[i][2] + bet0.z, acc[i][3] + bet0.w);
        float4 w1 = make_float4(acc[i][4] + bet1.x, acc[i][5] + bet1.y,
                                acc[i][6] + bet1.z, acc[i][7] + bet1.w);
        *(float4*)(outp) = w0;
        *(float4*)(outp + 4) = w1;
    }
}

// ---------------- K3: softmax stats + candidate-only gumbel argmax ----------------
// Winner of argmax(p + g) must have g >= g_rowmax - 1 (since 0 < p < 1). g is
// monotone in bits, so candidates are found by an integer compare against a
// conservatively relaxed bits-space threshold (~e candidates/row on average).
__global__ void __launch_bounds__(256) softmax_argmax_kernel() {
    const int n = blockIdx.x;
    const int tid = threadIdx.x;
    const float* row = g_L + (size_t)n * M_COLS;
    const uint32_t* brow = g_B + (size_t)n * M_COLS;

    float4 v0 = *(const float4*)(row + tid * 8);
    float4 v1 = *(const float4*)(row + tid * 8 + 4);
    float ev[8] = {v0.x, v0.y, v0.z, v0.w, v1.x, v1.y, v1.z, v1.w};
    uint4 b0 = *(const uint4*)(brow + tid * 8);
    uint4 b1 = *(const uint4*)(brow + tid * 8 + 4);
    uint32_t bits[8] = {b0.x, b0.y, b0.z, b0.w, b1.x, b1.y, b1.z, b1.w};

    __shared__ float sm[256];
    __shared__ uint32_t sb[256];
    // --- row max (logits) and row max (bits), fused reduction ---
    float lmax = ev[0];
    uint32_t bmax = bits[0];
#pragma unroll
    for (int i = 1; i < 8; i++) {
        lmax = fmaxf(lmax, ev[i]);
        bmax = max(bmax, bits[i]);
    }
    sm[tid] = lmax; sb[tid] = bmax;
    __syncthreads();
    for (int st = 128; st > 0; st >>= 1) {
        if (tid < st) {
            sm[tid] = fmaxf(sm[tid], sm[tid + st]);
            sb[tid] = max(sb[tid], sb[tid + st]);
        }
        __syncthreads();
    }
    float rmax = sm[0];
    uint32_t rbmax = sb[0];
    __syncthreads();
    // --- row sum of exp ---
    float ls = 0.f;
#pragma unroll
    for (int i = 0; i < 8; i++) { ev[i] = expf(ev[i] - rmax); ls += ev[i]; }
    sm[tid] = ls;
    __syncthreads();
    for (int st = 128; st > 0; st >>= 1) {
        if (tid < st) sm[tid] += sm[tid + st];
        __syncthreads();
    }
    const float rZ = 1.0f / sm[0];
    __syncthreads();

    // --- candidate threshold in bits space: g >= g_max - 1  (relaxed by 8 ulp of u) ---
    float gmaxv = gumbel_from_bits(rbmax);
    float t = gmaxv - 1.0f;
    float u_t = expf(-expf(-t));
    float mtf = floorf(u_t * 8388608.0f) - 8.0f;
    uint32_t mant_t = (mtf <= 0.f) ? 0u : (uint32_t)mtf;

    // --- argmax over candidates only ---
    float best = -3.4e38f;
    int bi = 0x7FFFFFFF;
#pragma unroll
    for (int i = 0; i < 8; i++) {
        if ((bits[i] >> 9) >= mant_t) {
            float s = ev[i] * rZ + gumbel_from_bits(bits[i]);
            if (s > best) { best = s; bi = tid * 8 + i; }  // ascending j keeps first index
        }
    }
    __shared__ int si[256];
    sm[tid] = best; si[tid] = bi;
    __syncthreads();
    for (int st = 128; st > 0; st >>= 1) {
        if (tid < st) {
            float v2 = sm[tid + st]; int i2 = si[tid + st];
            if (v2 > sm[tid] || (v2 == sm[tid] && i2 < si[tid])) { sm[tid] = v2; si[tid] = i2; }
        }
        __syncthreads();
    }
    if (tid == 0) g_idx[n] = si[0];
}

// ---------------- K5: acc = 0; acc[idx[n]] += x1[n] ----------------
__global__ void __launch_bounds__(256) zero_acc_kernel() {
    g_acc[blockIdx.x * 256 + threadIdx.x] = 0.f;
}

__global__ void __launch_bounds__(256) scatter_kernel(const float* __restrict__ x1) {
    const int w = threadIdx.x >> 5;
    const int lane = threadIdx.x & 31;
    const int n = blockIdx.x * 8 + w;
    const int m = g_idx[n];
#pragma unroll
    for (int i = 0; i < 4; i++) {
        int d = lane + i * 32;
        atomicAdd(&g_acc[m * DIM + d], x1[(size_t)n * DIM + d]);
    }
}

// ---------------- K6: out = acc @ Wd.T + bd ----------------
__global__ void __launch_bounds__(128) final_kernel(const float* __restrict__ Wd,
                                                    const float* __restrict__ bd,
                                                    float* __restrict__ out) {
    const int m = blockIdx.x;
    const int j = threadIdx.x;
    __shared__ float a[DIM];
    a[j] = g_acc[m * DIM + j];
    __syncthreads();
    float s = bd[j];
#pragma unroll 8
    for (int kq = 0; kq < DIM; kq++) s = fmaf(a[kq], Wd[j * DIM + kq], s);
    out[m * DIM + j] = s;
}

// ---------------- launch ----------------
extern "C" void kernel_launch(void* const* d_in, const int* in_sizes, int n_in,
                              void* d_out, int out_size) {
    const float* x1 = (const float*)d_in[0];
    const float* k  = (const float*)d_in[1];
    const float* c  = (const float*)d_in[2];
    const float* Wq = (const float*)d_in[3];
    const float* bq = (const float*)d_in[4];
    const float* Wd = (const float*)d_in[5];
    const float* bd = (const float*)d_in[6];
    float* out = (float*)d_out;

    prep_Wb_kernel<<<128, 128>>>(Wq, bq);
    prep_G_kernel<<<M_COLS, 128>>>(c);
    dim3 gl(M_COLS / BN, N_ROWS / BM);
    logits_kernel<<<gl, 256>>>(x1, k);
    softmax_argmax_kernel<<<N_ROWS, 256>>>();
    zero_acc_kernel<<<M_COLS * DIM / 256, 256>>>();
    scatter_kernel<<<N_ROWS / 8, 256>>>(x1);
    final_kernel<<<M_COLS, 128>>>(Wd, bd, out);
}

// round 7
// speedup vs baseline: 1.4786x; 1.4786x over previous
#include <cuda_runtime.h>
#include <cuda_bf16.h>
#include <math.h>
#include <stdint.h>

#define N_ROWS 32768
#define M_COLS 2048
#define DIM    128
#define HEADS  8

// ---------------- scratch ----------------
__device__ float    g_W[DIM * DIM];
__device__ float    g_bsum[DIM];
__device__ float    g_G[M_COLS * DIM];
__device__ float    g_beta[M_COLS];
__device__ float    g_L[(size_t)N_ROWS * M_COLS];   // logits, 256 MB
__device__ int      g_idx[N_ROWS];
__device__ float    g_acc[M_COLS * DIM];

// ---------------- K0a ----------------
__global__ void __launch_bounds__(128) prep_Wb_kernel(const float* __restrict__ Wq,
                                                      const float* __restrict__ bq) {
    int i = blockIdx.x, j = threadIdx.x;
    float s = 0.f;
#pragma unroll
    for (int h = 0; h < HEADS; h++) s += Wq[(h * DIM + i) * DIM + j];
    g_W[i * DIM + j] = s;
    if (i == 0) {
        float t = 0.f;
#pragma unroll
        for (int h = 0; h < HEADS; h++) t += bq[h * DIM + j];
        g_bsum[j] = 2.0f * t;
    }
}

// ---------------- K0b ----------------
__global__ void __launch_bounds__(128) prep_G_kernel(const float* __restrict__ c) {
    int m = blockIdx.x, kq = threadIdx.x;
    __shared__ float cs[DIM];
    __shared__ float red[DIM];
    cs[kq] = c[m * DIM + kq];
    __syncthreads();
    const float inv = 0.08838834764831845f;
    float s = 0.f;
#pragma unroll 8
    for (int j = 0; j < DIM; j++) s = fmaf(cs[j], g_W[j * DIM + kq], s);
    g_G[m * DIM + kq] = s * inv;
    red[kq] = cs[kq] * g_bsum[kq];
    __syncthreads();
    for (int st = 64; st > 0; st >>= 1) {
        if (kq < st) red[kq] += red[kq + st];
        __syncthreads();
    }
    if (kq == 0) g_beta[m] = red[0] * inv;
}

// ================= warp-MMA helpers (sm_80-era, compiles for plain compute_100) ======
__device__ __forceinline__ uint32_t smem_u32(const void* p) {
    uint32_t a;
    asm("{ .reg .u64 t; cvta.to.shared.u64 t, %1; cvt.u32.u64 %0, t; }" : "=r"(a) : "l"(p));
    return a;
}
__device__ __forceinline__ void ldsm_x4(uint32_t* r, uint32_t addr) {
    asm volatile("ldmatrix.sync.aligned.m8n8.x4.shared.b16 {%0,%1,%2,%3}, [%4];"
                 : "=r"(r[0]), "=r"(r[1]), "=r"(r[2]), "=r"(r[3]) : "r"(addr));
}
__device__ __forceinline__ void mma16816(float* c, const uint32_t* a, const uint32_t* b) {
    asm volatile(
        "mma.sync.aligned.m16n8k16.row.col.f32.bf16.bf16.f32 "
        "{%0,%1,%2,%3}, {%4,%5,%6,%7}, {%8,%9}, {%0,%1,%2,%3};"
        : "+f"(c[0]), "+f"(c[1]), "+f"(c[2]), "+f"(c[3])
        : "r"(a[0]), "r"(a[1]), "r"(a[2]), "r"(a[3]), "r"(b[0]), "r"(b[1]));
}
__device__ __forceinline__ void split_pack(const float* v, uint32_t* hp, uint32_t* lp) {
#pragma unroll
    for (int q = 0; q < 2; q++) {
        __nv_bfloat16 h0 = __float2bfloat16_rn(v[2 * q]);
        __nv_bfloat16 h1 = __float2bfloat16_rn(v[2 * q + 1]);
        __nv_bfloat16 l0 = __float2bfloat16_rn(v[2 * q] - __bfloat162float(h0));
        __nv_bfloat16 l1 = __float2bfloat16_rn(v[2 * q + 1] - __bfloat162float(h1));
        hp[q] = ((uint32_t)__bfloat16_as_ushort(h1) << 16) | __bfloat16_as_ushort(h0);
        lp[q] = ((uint32_t)__bfloat16_as_ushort(l1) << 16) | __bfloat16_as_ushort(l0);
    }
}

// ---------------- K2: logits = (x1+k) @ G^T + beta, bf16-split 3-pass mma.sync ------
// CTA tile 128x128, whole K=128 resident. smem: A_hi|A_lo|B_hi|B_lo, [128][136] bf16.
#define LDPAD 136
#define TILE_ELEMS (128 * LDPAD)
#define TILE_BYTES (TILE_ELEMS * 2)
#define GEMM_SMEM_BYTES (4 * TILE_BYTES)

__global__ void __launch_bounds__(256) logits_mma_kernel(const float* __restrict__ x1,
                                                         const float* __restrict__ kk) {
    extern __shared__ __nv_bfloat16 sm_[];
    __nv_bfloat16* sAh = sm_;
    __nv_bfloat16* sAl = sm_ + TILE_ELEMS;
    __nv_bfloat16* sBh = sm_ + 2 * TILE_ELEMS;
    __nv_bfloat16* sBl = sm_ + 3 * TILE_ELEMS;
    __shared__ float sBeta[128];

    const int tid = threadIdx.x;
    const int row0 = blockIdx.y * 128;
    const int col0 = blockIdx.x * 128;

    if (tid < 128) sBeta[tid] = g_beta[col0 + tid];

    // ---- load + split A = x1+k ----
#pragma unroll
    for (int i = 0; i < 16; i++) {
        int idx = i * 256 + tid;          // 4096 float4 slots
        int r = idx >> 5;
        int c4 = (idx & 31) * 4;
        float4 a4 = *(const float4*)(x1 + (size_t)(row0 + r) * DIM + c4);
        float4 b4 = *(const float4*)(kk + (size_t)(row0 + r) * DIM + c4);
        float v[4] = {a4.x + b4.x, a4.y + b4.y, a4.z + b4.z, a4.w + b4.w};
        uint32_t hp[2], lp[2];
        split_pack(v, hp, lp);
        *(uint2*)(sAh + r * LDPAD + c4) = make_uint2(hp[0], hp[1]);
        *(uint2*)(sAl + r * LDPAD + c4) = make_uint2(lp[0], lp[1]);
    }
    // ---- load + split B = G rows ----
#pragma unroll
    for (int i = 0; i < 16; i++) {
        int idx = i * 256 + tid;
        int r = idx >> 5;
        int c4 = (idx & 31) * 4;
        float4 g4 = *(const float4*)(g_G + (size_t)(col0 + r) * DIM + c4);
        float v[4] = {g4.x, g4.y, g4.z, g4.w};
        uint32_t hp[2], lp[2];
        split_pack(v, hp, lp);
        *(uint2*)(sBh + r * LDPAD + c4) = make_uint2(hp[0], hp[1]);
        *(uint2*)(sBl + r * LDPAD + c4) = make_uint2(lp[0], lp[1]);
    }
    __syncthreads();

    // ---- warp tiling: 8 warps = 2 (m) x 4 (n); warp tile 64x32 ----
    const int wid = tid >> 5;
    const int lane = tid & 31;
    const int wm = wid & 1;           // 0..1
    const int wn = wid >> 1;          // 0..3
    const int mW = wm * 64;
    const int nW = wn * 32;

    // ldmatrix lane address offsets
    const int g = lane >> 3, li = lane & 7;
    const int aRow = ((g & 1) << 3) + li, aCol = (g & 2) << 2;   // A groups: m0-7,k0 / m8-15,k0 / m0-7,k8 / m8-15,k8
    const int bRow = ((g >> 1) << 3) + li, bCol = (g & 1) << 3;  // B groups: n0-7,k0 / n0-7,k8 / n8-15,k0 / n8-15,k8

    const uint32_t aBaseH = smem_u32(sAh) + (uint32_t)(((mW + aRow) * LDPAD + aCol) * 2);
    const uint32_t bBaseH = smem_u32(sBh) + (uint32_t)(((nW + bRow) * LDPAD + bCol) * 2);
    const uint32_t LO_OFF = (uint32_t)TILE_BYTES;   // hi tile -> lo tile

    float acc[4][4][4];
#pragma unroll
    for (int mt = 0; mt < 4; mt++)
#pragma unroll
        for (int nt = 0; nt < 4; nt++)
#pragma unroll
            for (int q = 0; q < 4; q++) acc[mt][nt][q] = 0.f;

#pragma unroll
    for (int ks = 0; ks < 8; ks++) {
        uint32_t ah[16], bh[8], bl[8];
        const uint32_t kOff = (uint32_t)(ks * 32);   // 16 bf16 = 32 B
#pragma unroll
        for (int mt = 0; mt < 4; mt++) ldsm_x4(&ah[4 * mt], aBaseH + mt * (16 * LDPAD * 2) + kOff);
#pragma unroll
        for (int np = 0; np < 2; np++) ldsm_x4(&bh[4 * np], bBaseH + np * (16 * LDPAD * 2) + kOff);
        // pass 0: Ahi * Bhi
#pragma unroll
        for (int mt = 0; mt < 4; mt++)
#pragma unroll
            for (int nt = 0; nt < 4; nt++) mma16816(acc[mt][nt], &ah[4 * mt], &bh[2 * nt]);
        // pass 1: Ahi * Blo
#pragma unroll
        for (int np = 0; np < 2; np++) ldsm_x4(&bl[4 * np], bBaseH + LO_OFF + np * (16 * LDPAD * 2) + kOff);
#pragma unroll
        for (int mt = 0; mt < 4; mt++)
#pragma unroll
            for (int nt = 0; nt < 4; nt++) mma16816(acc[mt][nt], &ah[4 * mt], &bl[2 * nt]);
        // pass 2: Alo * Bhi (reuse ah regs)
#pragma unroll
        for (int mt = 0; mt < 4; mt++) ldsm_x4(&ah[4 * mt], aBaseH + LO_OFF + mt * (16 * LDPAD * 2) + kOff);
#pragma unroll
        for (int mt = 0; mt < 4; mt++)
#pragma unroll
            for (int nt = 0; nt < 4; nt++) mma16816(acc[mt][nt], &ah[4 * mt], &bh[2 * nt]);
    }

    // ---- epilogue: c-frag lane l holds (m=l/4, n=2*(l%4)) (+1), (m+8, n)(+1) ----
    const int rl = lane >> 2;
    const int cl = (lane & 3) * 2;
#pragma unroll
    for (int mt = 0; mt < 4; mt++) {
#pragma unroll
        for (int nt = 0; nt < 4; nt++) {
            int m = row0 + mW + mt * 16 + rl;
            int nn = nW + nt * 8 + cl;
            float b0 = sBeta[nn], b1 = sBeta[nn + 1];
            float* p0 = g_L + (size_t)m * M_COLS + col0 + nn;
            float* p1 = g_L + (size_t)(m + 8) * M_COLS + col0 + nn;
            *(float2*)p0 = make_float2(acc[mt][nt][0] + b0, acc[mt][nt][1] + b1);
            *(float2*)p1 = make_float2(acc[mt][nt][2] + b0, acc[mt][nt][3] + b1);
        }
    }
}

// ---------------- threefry2x32 (JAX, key=(0,42)) ----------------
__device__ __forceinline__ void threefry2x32_042(uint32_t x0, uint32_t x1,
                                                 uint32_t& o0, uint32_t& o1) {
    const uint32_t KS0 = 0u, KS1 = 42u, KS2 = 0x1BD11BDAu ^ 42u;
    x0 += KS0; x1 += KS1;
#define TF_R(r) { x0 += x1; x1 = __funnelshift_l(x1, x1, r); x1 ^= x0; }
    TF_R(13) TF_R(15) TF_R(26) TF_R(6)   x0 += KS1; x1 += KS2 + 1u;
    TF_R(17) TF_R(29) TF_R(16) TF_R(24)  x0 += KS2; x1 += KS0 + 2u;
    TF_R(13) TF_R(15) TF_R(26) TF_R(6)   x0 += KS0; x1 += KS1 + 3u;
    TF_R(17) TF_R(29) TF_R(16) TF_R(24)  x0 += KS1; x1 += KS2 + 4u;
    TF_R(13) TF_R(15) TF_R(26) TF_R(6)   x0 += KS2; x1 += KS0 + 5u;
#undef TF_R
    o0 = x0; o1 = x1;
}
__device__ __forceinline__ uint32_t tf_bits(uint32_t f) {
    uint32_t o0, o1;
    threefry2x32_042(0u, f, o0, o1);
    return o0 ^ o1;
}
__device__ __forceinline__ float gumbel_from_bits(uint32_t bits) {
    float u = __uint_as_float((bits >> 9) | 0x3f800000u) - 1.0f;
    u = fmaxf(u, 1.17549435e-38f);
    return -logf(-logf(u));
}

// ---------------- K3: inline threefry + softmax + candidate argmax ----------------
__global__ void __launch_bounds__(256) softmax_argmax_kernel() {
    const int n = blockIdx.x;
    const int tid = threadIdx.x;
    const float* row = g_L + (size_t)n * M_COLS;

    float4 v0 = *(const float4*)(row + tid * 8);
    float4 v1 = *(const float4*)(row + tid * 8 + 4);
    float ev[8] = {v0.x, v0.y, v0.z, v0.w, v1.x, v1.y, v1.z, v1.w};

    uint32_t bits[8];
    const uint32_t fbase = (uint32_t)(n * M_COLS) + (uint32_t)(tid * 8);
#pragma unroll
    for (int i = 0; i < 8; i++) bits[i] = tf_bits(fbase + (uint32_t)i);

    __shared__ float sm[256];
    __shared__ uint32_t sb[256];
    float lmax = ev[0];
    uint32_t bmax = bits[0];
#pragma unroll
    for (int i = 1; i < 8; i++) { lmax = fmaxf(lmax, ev[i]); bmax = max(bmax, bits[i]); }
    sm[tid] = lmax; sb[tid] = bmax;
    __syncthreads();
    for (int st = 128; st > 0; st >>= 1) {
        if (tid < st) {
            sm[tid] = fmaxf(sm[tid], sm[tid + st]);
            sb[tid] = max(sb[tid], sb[tid + st]);
        }
        __syncthreads();
    }
    float rmax = sm[0];
    uint32_t rbmax = sb[0];
    __syncthreads();
    float ls = 0.f;
#pragma unroll
    for (int i = 0; i < 8; i++) { ev[i] = expf(ev[i] - rmax); ls += ev[i]; }
    sm[tid] = ls;
    __syncthreads();
    for (int st = 128; st > 0; st >>= 1) {
        if (tid < st) sm[tid] += sm[tid + st];
        __syncthreads();
    }
    const float rZ = 1.0f / sm[0];
    __syncthreads();

    // winner needs g >= g_max - 1 (since 0 < p < 1); relax threshold by 8 mantissa ulp
    float gmaxv = gumbel_from_bits(rbmax);
    float t = gmaxv - 1.0f;
    float u_t = expf(-expf(-t));
    float mtf = floorf(u_t * 8388608.0f) - 8.0f;
    uint32_t mant_t = (mtf <= 0.f) ? 0u : (uint32_t)mtf;

    float best = -3.4e38f;
    int bi = 0x7FFFFFFF;
#pragma unroll
    for (int i = 0; i < 8; i++) {
        if ((bits[i] >> 9) >= mant_t) {
            float s = ev[i] * rZ + gumbel_from_bits(bits[i]);
            if (s > best) { best = s; bi = tid * 8 + i; }
        }
    }
    __shared__ int si[256];
    sm[tid] = best; si[tid] = bi;
    __syncthreads();
    for (int st = 128; st > 0; st >>= 1) {
        if (tid < st) {
            float v2 = sm[tid + st]; int i2 = si[tid + st];
            if (v2 > sm[tid] || (v2 == sm[tid] && i2 < si[tid])) { sm[tid] = v2; si[tid] = i2; }
        }
        __syncthreads();
    }
    if (tid == 0) g_idx[n] = si[0];
}

// ---------------- K5/K6 ----------------
__global__ void __launch_bounds__(256) zero_acc_kernel() {
    g_acc[blockIdx.x * 256 + threadIdx.x] = 0.f;
}
__global__ void __launch_bounds__(256) scatter_kernel(const float* __restrict__ x1) {
    const int w = threadIdx.x >> 5;
    const int lane = threadIdx.x & 31;
    const int n = blockIdx.x * 8 + w;
    const int m = g_idx[n];
#pragma unroll
    for (int i = 0; i < 4; i++) {
        int d = lane + i * 32;
        atomicAdd(&g_acc[m * DIM + d], x1[(size_t)n * DIM + d]);
    }
}
__global__ void __launch_bounds__(128) final_kernel(const float* __restrict__ Wd,
                                                    const float* __restrict__ bd,
                                                    float* __restrict__ out) {
    const int m = blockIdx.x;
    const int j = threadIdx.x;
    __shared__ float a[DIM];
    a[j] = g_acc[m * DIM + j];
    __syncthreads();
    float s = bd[j];
#pragma unroll 8
    for (int kq = 0; kq < DIM; kq++) s = fmaf(a[kq], Wd[j * DIM + kq], s);
    out[m * DIM + j] = s;
}

// ---------------- launch ----------------
extern "C" void kernel_launch(void* const* d_in, const int* in_sizes, int n_in,
                              void* d_out, int out_size) {
    const float* x1 = (const float*)d_in[0];
    const float* k  = (const float*)d_in[1];
    const float* c  = (const float*)d_in[2];
    const float* Wq = (const float*)d_in[3];
    const float* bq = (const float*)d_in[4];
    const float* Wd = (const float*)d_in[5];
    const float* bd = (const float*)d_in[6];
    float* out = (float*)d_out;

    cudaFuncSetAttribute(logits_mma_kernel,
                         cudaFuncAttributeMaxDynamicSharedMemorySize, GEMM_SMEM_BYTES);

    prep_Wb_kernel<<<128, 128>>>(Wq, bq);
    prep_G_kernel<<<M_COLS, 128>>>(c);
    dim3 gl(M_COLS / 128, N_ROWS / 128);
    logits_mma_kernel<<<gl, 256, GEMM_SMEM_BYTES>>>(x1, k);
    softmax_argmax_kernel<<<N_ROWS, 256>>>();
    zero_acc_kernel<<<M_COLS * DIM / 256, 256>>>();
    scatter_kernel<<<N_ROWS / 8, 256>>>(x1);
    final_kernel<<<M_COLS, 128>>>(Wd, bd, out);
}